// round 5
// baseline (speedup 1.0000x reference)
#include <cuda_runtime.h>
#include <math.h>

typedef unsigned long long ull;

__device__ __forceinline__ ull pack2(float lo, float hi) {
    ull r; asm("mov.b64 %0, {%1,%2};" : "=l"(r) : "f"(lo), "f"(hi)); return r;
}
__device__ __forceinline__ void unpack2(ull v, float& lo, float& hi) {
    asm("mov.b64 {%0,%1}, %2;" : "=f"(lo), "=f"(hi) : "l"(v));
}
__device__ __forceinline__ ull fma2(ull a, ull b, ull c) {
    ull d; asm("fma.rn.f32x2 %0, %1, %2, %3;" : "=l"(d) : "l"(a), "l"(b), "l"(c)); return d;
}
__device__ __forceinline__ ull add2(ull a, ull b) {
    ull d; asm("add.rn.f32x2 %0, %1, %2;" : "=l"(d) : "l"(a), "l"(b)); return d;
}

// Block handles 16 batch rows. 8 warps = 4 row-groups x 2 pixel-halves.
// smem: permuted weights [p][k] (784x10 f32), per-pixel (alpha,beta) (784 f2),
// cross-warp partial sums sred[8][4][10].
__global__ __launch_bounds__(256, 3)
void quanv_fused(const float* __restrict__ x,
                 const float* __restrict__ params,
                 const float* __restrict__ w,
                 const float* __restrict__ bias,
                 float* __restrict__ out) {
    __shared__ float  sw[784 * 10];     // 31360 B, layout [p][k], stride 10
    __shared__ float2 sab[784];         //  6272 B
    __shared__ float  sred[8][4][10];   //  1280 B

    const int tid = threadIdx.x;

    // ---- init: per-channel SU(2) observable coefficients (every thread) ----
    float al[4], be[4];
#pragma unroll
    for (int c = 0; c < 4; c++) {
        float u00r = 1.f, u00i = 0.f, u01r = 0.f, u01i = 0.f;
        float u10r = 0.f, u10i = 0.f, u11r = 1.f, u11i = 0.f;
        for (int d = 0; d < 4; d++) {
            float rz1 = params[(d * 4 + c) * 3 + 0];
            float ry  = params[(d * 4 + c) * 3 + 1];
            float rz2 = params[(d * 4 + c) * 3 + 2];
            {   // Rz(rz1): row0 *= e^{-i ph}, row1 *= e^{+i ph}
                float ph = 0.5f * rz1;
                float cr = cosf(ph), ci = -sinf(ph);
                float t_;
                t_ = u00r * cr - u00i * ci; u00i = u00r * ci + u00i * cr; u00r = t_;
                t_ = u01r * cr - u01i * ci; u01i = u01r * ci + u01i * cr; u01r = t_;
                t_ = u10r * cr + u10i * ci; u10i = -u10r * ci + u10i * cr; u10r = t_;
                t_ = u11r * cr + u11i * ci; u11i = -u11r * ci + u11i * cr; u11r = t_;
            }
            {   // Ry(ry)
                float cc = cosf(0.5f * ry), ss = sinf(0.5f * ry);
                float n00r = cc * u00r - ss * u10r, n00i = cc * u00i - ss * u10i;
                float n01r = cc * u01r - ss * u11r, n01i = cc * u01i - ss * u11i;
                float n10r = ss * u00r + cc * u10r, n10i = ss * u00i + cc * u10i;
                float n11r = ss * u01r + cc * u11r, n11i = ss * u01i + cc * u11i;
                u00r = n00r; u00i = n00i; u01r = n01r; u01i = n01i;
                u10r = n10r; u10i = n10i; u11r = n11r; u11i = n11i;
            }
            {   // Rz(rz2)
                float ph = 0.5f * rz2;
                float cr = cosf(ph), ci = -sinf(ph);
                float t_;
                t_ = u00r * cr - u00i * ci; u00i = u00r * ci + u00i * cr; u00r = t_;
                t_ = u01r * cr - u01i * ci; u01i = u01r * ci + u01i * cr; u01r = t_;
                t_ = u10r * cr + u10i * ci; u10i = -u10r * ci + u10i * cr; u10r = t_;
                t_ = u11r * cr + u11i * ci; u11i = -u11r * ci + u11i * cr; u11r = t_;
            }
        }
        al[c] = (u00r * u00r + u00i * u00i) - (u10r * u10r + u10i * u10i);
        be[c] = (u00r * u01r + u00i * u01i) - (u10r * u11r + u10i * u11i);
    }

    // per-pixel (alpha, beta): channel = ((p/28)&1)*2 + (p&1)
    for (int p = tid; p < 784; p += 256) {
        int r = p / 28;
        int ch = ((r & 1) << 1) | (p & 1);
        sab[p] = make_float2(al[ch], be[ch]);
    }
    // permuted weights into [p][k]
    for (int idx = tid; idx < 7840; idx += 256) {
        int p = idx / 10;
        int k = idx - p * 10;
        int r = p / 28, c = p - r * 28;
        int i = r >> 1, di = r & 1;
        int j = c >> 1, dj = c & 1;
        int f = (i * 14 + j) * 4 + (di * 2 + dj);
        sw[idx] = w[k * 784 + f];
    }
    __syncthreads();

    // ---- main loop ----
    const int warp = tid >> 5;
    const int lane = tid & 31;
    const int g = warp >> 1;        // row-group 0..3
    const int h = warp & 1;         // pixel half
    const float* xp = x + ((size_t)blockIdx.x * 16 + g * 4) * 784;

    ull acc[4][5];
#pragma unroll
    for (int r = 0; r < 4; r++)
#pragma unroll
        for (int kk = 0; kk < 5; kk++) acc[r][kk] = 0ull;

    const int t0 = h ? 13 : 0;
    const int t1 = h ? 25 : 13;
#pragma unroll 2
    for (int t = t0; t < t1; t++) {
        int p = t * 32 + lane;
        bool valid = (p < 784);
        int pc = valid ? p : 0;
        float2 ab = sab[pc];
        ull fd[4];
#pragma unroll
        for (int r = 0; r < 4; r++) {
            float v = __ldg(xp + r * 784 + pc);
            float s, c;
            __sincosf(v, &s, &c);
            float fv = fmaf(ab.x, c, ab.y * s);
            fv = valid ? fv : 0.f;
            fd[r] = pack2(fv, fv);
        }
        const float* wrow = &sw[pc * 10];
#pragma unroll
        for (int kk = 0; kk < 5; kk++) {
            ull wv;
            {
                double dv = *reinterpret_cast<const double*>(wrow + kk * 2);
                wv = __double_as_longlong(dv);
            }
#pragma unroll
            for (int r = 0; r < 4; r++)
                acc[r][kk] = fma2(fd[r], wv, acc[r][kk]);
        }
    }

    // ---- warp butterfly reduce (packed) ----
#pragma unroll
    for (int r = 0; r < 4; r++)
#pragma unroll
        for (int kk = 0; kk < 5; kk++) {
            ull v = acc[r][kk];
            v = add2(v, __shfl_xor_sync(0xFFFFFFFFu, v, 16));
            v = add2(v, __shfl_xor_sync(0xFFFFFFFFu, v, 8));
            v = add2(v, __shfl_xor_sync(0xFFFFFFFFu, v, 4));
            v = add2(v, __shfl_xor_sync(0xFFFFFFFFu, v, 2));
            v = add2(v, __shfl_xor_sync(0xFFFFFFFFu, v, 1));
            acc[r][kk] = v;
        }

    // extract class value per lane, stash partials
#pragma unroll
    for (int r = 0; r < 4; r++) {
        float myv = 0.f;
#pragma unroll
        for (int k = 0; k < 10; k++) {
            float lo, hi;
            unpack2(acc[r][k >> 1], lo, hi);
            float comp = (k & 1) ? hi : lo;
            if (lane == k) myv = comp;
        }
        if (lane < 10) sred[warp][r][lane] = myv;
    }
    __syncthreads();

    // ---- final: combine halves + log-softmax (16 threads, one per row) ----
    if (tid < 16) {
        int gg = tid >> 2, rr = tid & 3;
        float l[10];
#pragma unroll
        for (int k = 0; k < 10; k++)
            l[k] = sred[2 * gg][rr][k] + sred[2 * gg + 1][rr][k] + bias[k];
        float m = l[0];
#pragma unroll
        for (int k = 1; k < 10; k++) m = fmaxf(m, l[k]);
        float sum = 0.f;
#pragma unroll
        for (int k = 0; k < 10; k++) sum += __expf(l[k] - m);
        float lse = m + __logf(sum);
        size_t row = (size_t)blockIdx.x * 16 + gg * 4 + rr;
#pragma unroll
        for (int k = 0; k < 10; k++)
            out[row * 10 + k] = l[k] - lse;
    }
}

extern "C" void kernel_launch(void* const* d_in, const int* in_sizes, int n_in,
                              void* d_out, int out_size) {
    const float* x      = (const float*)d_in[0];   // (8192,1,28,28)
    const float* params = (const float*)d_in[1];   // (4,4,3)
    const float* w      = (const float*)d_in[2];   // (10,784)
    const float* bias   = (const float*)d_in[3];   // (10,)
    float* out          = (float*)d_out;           // (8192,10)

    quanv_fused<<<512, 256>>>(x, params, w, bias, out);
}

// round 9
// speedup vs baseline: 1.4087x; 1.4087x over previous
#include <cuda_runtime.h>
#include <math.h>

typedef unsigned long long ull;

__device__ __forceinline__ ull pack2(float lo, float hi) {
    ull r; asm("mov.b64 %0, {%1,%2};" : "=l"(r) : "f"(lo), "f"(hi)); return r;
}
__device__ __forceinline__ void unpack2(ull v, float& lo, float& hi) {
    asm("mov.b64 {%0,%1}, %2;" : "=f"(lo), "=f"(hi) : "l"(v));
}
__device__ __forceinline__ ull fma2(ull a, ull b, ull c) {
    ull d; asm("fma.rn.f32x2 %0, %1, %2, %3;" : "=l"(d) : "l"(a), "l"(b), "l"(c)); return d;
}
__device__ __forceinline__ ull add2(ull a, ull b) {
    ull d; asm("add.rn.f32x2 %0, %1, %2;" : "=l"(d) : "l"(a), "l"(b)); return d;
}

// Block = 16 batch rows. 8 warps = 4 row-groups x 2 pixel-halves.
// smem: sw2[kk][p] = (w'[2kk][p], w'[2kk+1][p])  -- conflict-free LDS.64 by lane=pixel.
__global__ __launch_bounds__(256, 3)
void quanv_fused(const float* __restrict__ x,
                 const float* __restrict__ params,
                 const float* __restrict__ w,
                 const float* __restrict__ bias,
                 float* __restrict__ out) {
    __shared__ float2 sw2[5 * 784];     // 31360 B
    __shared__ float  sred[8][4][10];   //  1280 B
    __shared__ float  s_al[4], s_be[4];

    const int tid = threadIdx.x;

    // ---- SU(2) observable coefficients: 4 threads only, fast intrinsics ----
    if (tid < 4) {
        const int c = tid;
        float u00r = 1.f, u00i = 0.f, u01r = 0.f, u01i = 0.f;
        float u10r = 0.f, u10i = 0.f, u11r = 1.f, u11i = 0.f;
        for (int d = 0; d < 4; d++) {
            float rz1 = params[(d * 4 + c) * 3 + 0];
            float ry  = params[(d * 4 + c) * 3 + 1];
            float rz2 = params[(d * 4 + c) * 3 + 2];
            {   // Rz(rz1): row0 *= e^{-i ph}, row1 *= e^{+i ph}
                float sp, cp; __sincosf(0.5f * rz1, &sp, &cp);
                float ci = -sp, cr = cp, t_;
                t_ = u00r * cr - u00i * ci; u00i = u00r * ci + u00i * cr; u00r = t_;
                t_ = u01r * cr - u01i * ci; u01i = u01r * ci + u01i * cr; u01r = t_;
                t_ = u10r * cr + u10i * ci; u10i = -u10r * ci + u10i * cr; u10r = t_;
                t_ = u11r * cr + u11i * ci; u11i = -u11r * ci + u11i * cr; u11r = t_;
            }
            {   // Ry(ry)
                float ss, cc; __sincosf(0.5f * ry, &ss, &cc);
                float n00r = cc * u00r - ss * u10r, n00i = cc * u00i - ss * u10i;
                float n01r = cc * u01r - ss * u11r, n01i = cc * u01i - ss * u11i;
                float n10r = ss * u00r + cc * u10r, n10i = ss * u00i + cc * u10i;
                float n11r = ss * u01r + cc * u11r, n11i = ss * u01i + cc * u11i;
                u00r = n00r; u00i = n00i; u01r = n01r; u01i = n01i;
                u10r = n10r; u10i = n10i; u11r = n11r; u11i = n11i;
            }
            {   // Rz(rz2)
                float sp, cp; __sincosf(0.5f * rz2, &sp, &cp);
                float ci = -sp, cr = cp, t_;
                t_ = u00r * cr - u00i * ci; u00i = u00r * ci + u00i * cr; u00r = t_;
                t_ = u01r * cr - u01i * ci; u01i = u01r * ci + u01i * cr; u01r = t_;
                t_ = u10r * cr + u10i * ci; u10i = -u10r * ci + u10i * cr; u10r = t_;
                t_ = u11r * cr + u11i * ci; u11i = -u11r * ci + u11i * cr; u11r = t_;
            }
        }
        s_al[c] = (u00r * u00r + u00i * u00i) - (u10r * u10r + u10i * u10i);
        s_be[c] = (u00r * u01r + u00i * u01i) - (u10r * u11r + u10i * u11i);
    }

    // ---- permuted weights into [kk][p] float2 (class-pair interleave) ----
    for (int p = tid; p < 784; p += 256) {
        int r = p / 28, c = p - r * 28;
        int f = ((r >> 1) * 14 + (c >> 1)) * 4 + ((r & 1) << 1) + (c & 1);
#pragma unroll
        for (int kk = 0; kk < 5; kk++)
            sw2[kk * 784 + p] = make_float2(w[(2 * kk) * 784 + f],
                                            w[(2 * kk + 1) * 784 + f]);
    }
    __syncthreads();

    // ---- main loop ----
    const int warp = tid >> 5;
    const int lane = tid & 31;
    const int g = warp >> 1;        // row-group 0..3
    const int h = warp & 1;         // pixel half
    // channel = ((rowparity)<<1) | (p&1); p&1 == lane&1 (fixed per thread)
    const float al0 = s_al[lane & 1],       be0 = s_be[lane & 1];
    const float al1 = s_al[2 | (lane & 1)], be1 = s_be[2 | (lane & 1)];
    const float* xp = x + ((size_t)blockIdx.x * 16 + g * 4) * 784;

    ull acc[4][5];
#pragma unroll
    for (int r = 0; r < 4; r++)
#pragma unroll
        for (int kk = 0; kk < 5; kk++) acc[r][kk] = 0ull;

    const int t0 = h ? 13 : 0;
    const int t1 = h ? 24 : 13;
    for (int t = t0; t < t1; t++) {
        int p = t * 32 + lane;
        int r28 = p / 28;
        bool odd = (r28 & 1);
        float A = odd ? al1 : al0;
        float Bq = odd ? be1 : be0;
        ull fd[4];
#pragma unroll
        for (int r = 0; r < 4; r++) {
            float v = __ldg(xp + r * 784 + p);
            float s, c;
            __sincosf(v, &s, &c);
            float fv = fmaf(A, c, Bq * s);
            fd[r] = pack2(fv, fv);
        }
#pragma unroll
        for (int kk = 0; kk < 5; kk++) {
            ull wv = *reinterpret_cast<const ull*>(&sw2[kk * 784 + p]);
#pragma unroll
            for (int r = 0; r < 4; r++)
                acc[r][kk] = fma2(fd[r], wv, acc[r][kk]);
        }
    }
    if (h) {
        // tail t=24: pixels 768..783, all in image row 27 (odd) -> al1/be1
        int p = 768 + lane;
        bool valid = (lane < 16);
        int pc = valid ? p : 768;
        ull fd[4];
#pragma unroll
        for (int r = 0; r < 4; r++) {
            float v = __ldg(xp + r * 784 + pc);
            float s, c;
            __sincosf(v, &s, &c);
            float fv = fmaf(al1, c, be1 * s);
            fv = valid ? fv : 0.f;
            fd[r] = pack2(fv, fv);
        }
#pragma unroll
        for (int kk = 0; kk < 5; kk++) {
            ull wv = *reinterpret_cast<const ull*>(&sw2[kk * 784 + pc]);
#pragma unroll
            for (int r = 0; r < 4; r++)
                acc[r][kk] = fma2(fd[r], wv, acc[r][kk]);
        }
    }

    // ---- warp butterfly reduce (packed) ----
#pragma unroll
    for (int r = 0; r < 4; r++)
#pragma unroll
        for (int kk = 0; kk < 5; kk++) {
            ull v = acc[r][kk];
            v = add2(v, __shfl_xor_sync(0xFFFFFFFFu, v, 16));
            v = add2(v, __shfl_xor_sync(0xFFFFFFFFu, v, 8));
            v = add2(v, __shfl_xor_sync(0xFFFFFFFFu, v, 4));
            v = add2(v, __shfl_xor_sync(0xFFFFFFFFu, v, 2));
            v = add2(v, __shfl_xor_sync(0xFFFFFFFFu, v, 1));
            acc[r][kk] = v;
        }

    // extract class value per lane, stash partials
#pragma unroll
    for (int r = 0; r < 4; r++) {
        float myv = 0.f;
#pragma unroll
        for (int k = 0; k < 10; k++) {
            float lo, hi;
            unpack2(acc[r][k >> 1], lo, hi);
            float comp = (k & 1) ? hi : lo;
            if (lane == k) myv = comp;
        }
        if (lane < 10) sred[warp][r][lane] = myv;
    }
    __syncthreads();

    // ---- final: combine halves + log-softmax (16 threads, one per row) ----
    if (tid < 16) {
        int gg = tid >> 2, rr = tid & 3;
        float l[10];
#pragma unroll
        for (int k = 0; k < 10; k++)
            l[k] = sred[2 * gg][rr][k] + sred[2 * gg + 1][rr][k] + bias[k];
        float m = l[0];
#pragma unroll
        for (int k = 1; k < 10; k++) m = fmaxf(m, l[k]);
        float sum = 0.f;
#pragma unroll
        for (int k = 0; k < 10; k++) sum += __expf(l[k] - m);
        float lse = m + __logf(sum);
        size_t row = (size_t)blockIdx.x * 16 + gg * 4 + rr;
#pragma unroll
        for (int k = 0; k < 10; k++)
            out[row * 10 + k] = l[k] - lse;
    }
}

extern "C" void kernel_launch(void* const* d_in, const int* in_sizes, int n_in,
                              void* d_out, int out_size) {
    const float* x      = (const float*)d_in[0];   // (8192,1,28,28)
    const float* params = (const float*)d_in[1];   // (4,4,3)
    const float* w      = (const float*)d_in[2];   // (10,784)
    const float* bias   = (const float*)d_in[3];   // (10,)
    float* out          = (float*)d_out;           // (8192,10)

    quanv_fused<<<512, 256>>>(x, params, w, bias, out);
}

// round 10
// speedup vs baseline: 2.0890x; 1.4830x over previous
#include <cuda_runtime.h>
#include <math.h>

typedef unsigned long long ull;

__device__ __forceinline__ ull pack2(float lo, float hi) {
    ull r; asm("mov.b64 %0, {%1,%2};" : "=l"(r) : "f"(lo), "f"(hi)); return r;
}
__device__ __forceinline__ void unpack2(ull v, float& lo, float& hi) {
    asm("mov.b64 {%0,%1}, %2;" : "=f"(lo), "=f"(hi) : "l"(v));
}
__device__ __forceinline__ ull fma2(ull a, ull b, ull c) {
    ull d; asm("fma.rn.f32x2 %0, %1, %2, %3;" : "=l"(d) : "l"(a), "l"(b), "l"(c)); return d;
}
__device__ __forceinline__ ull mul2(ull a, ull b) {
    ull d; asm("mul.rn.f32x2 %0, %1, %2;" : "=l"(d) : "l"(a), "l"(b)); return d;
}
__device__ __forceinline__ ull add2(ull a, ull b) {
    ull d; asm("add.rn.f32x2 %0, %1, %2;" : "=l"(d) : "l"(a), "l"(b)); return d;
}

// Block = 16 batch rows. 8 warps = 4 row-groups x 2 pixel-pair halves.
// x read as float2 pixel pairs (392 pairs/row); weights in smem as
// swp[kk][pair] = (w[2kk][p0], w[2kk+1][p0], w[2kk][p1], w[2kk+1][p1]).
__global__ __launch_bounds__(256, 3)
void quanv_fused(const float* __restrict__ x,
                 const float* __restrict__ params,
                 const float* __restrict__ w,
                 const float* __restrict__ bias,
                 float* __restrict__ out) {
    __shared__ float4 swp[5 * 392];     // 31360 B
    __shared__ float  sred[8][4][10];   //  1280 B
    __shared__ float  s_al[4], s_be[4];

    const int tid = threadIdx.x;

    // ---- SU(2) observable coefficients: 4 threads, fast intrinsics ----
    if (tid < 4) {
        const int c = tid;
        float u00r = 1.f, u00i = 0.f, u01r = 0.f, u01i = 0.f;
        float u10r = 0.f, u10i = 0.f, u11r = 1.f, u11i = 0.f;
        for (int d = 0; d < 4; d++) {
            float rz1 = params[(d * 4 + c) * 3 + 0];
            float ry  = params[(d * 4 + c) * 3 + 1];
            float rz2 = params[(d * 4 + c) * 3 + 2];
            {
                float sp, cp; __sincosf(0.5f * rz1, &sp, &cp);
                float ci = -sp, cr = cp, t_;
                t_ = u00r * cr - u00i * ci; u00i = u00r * ci + u00i * cr; u00r = t_;
                t_ = u01r * cr - u01i * ci; u01i = u01r * ci + u01i * cr; u01r = t_;
                t_ = u10r * cr + u10i * ci; u10i = -u10r * ci + u10i * cr; u10r = t_;
                t_ = u11r * cr + u11i * ci; u11i = -u11r * ci + u11i * cr; u11r = t_;
            }
            {
                float ss, cc; __sincosf(0.5f * ry, &ss, &cc);
                float n00r = cc * u00r - ss * u10r, n00i = cc * u00i - ss * u10i;
                float n01r = cc * u01r - ss * u11r, n01i = cc * u01i - ss * u11i;
                float n10r = ss * u00r + cc * u10r, n10i = ss * u00i + cc * u10i;
                float n11r = ss * u01r + cc * u11r, n11i = ss * u01i + cc * u11i;
                u00r = n00r; u00i = n00i; u01r = n01r; u01i = n01i;
                u10r = n10r; u10i = n10i; u11r = n11r; u11i = n11i;
            }
            {
                float sp, cp; __sincosf(0.5f * rz2, &sp, &cp);
                float ci = -sp, cr = cp, t_;
                t_ = u00r * cr - u00i * ci; u00i = u00r * ci + u00i * cr; u00r = t_;
                t_ = u01r * cr - u01i * ci; u01i = u01r * ci + u01i * cr; u01r = t_;
                t_ = u10r * cr + u10i * ci; u10i = -u10r * ci + u10i * cr; u10r = t_;
                t_ = u11r * cr + u11i * ci; u11i = -u11r * ci + u11i * cr; u11r = t_;
            }
        }
        s_al[c] = (u00r * u00r + u00i * u00i) - (u10r * u10r + u10i * u10i);
        s_be[c] = (u00r * u01r + u00i * u01i) - (u10r * u11r + u10i * u11i);
    }

    // ---- permuted weights: pair j -> pixels (2j, 2j+1), same image row ----
    for (int j = tid; j < 392; j += 256) {
        int p0 = 2 * j;
        int r = p0 / 28, c = p0 - r * 28;           // c even
        int f0 = ((r >> 1) * 14 + (c >> 1)) * 4 + ((r & 1) << 1);  // +(c&1)=0
        int f1 = f0 + 1;
#pragma unroll
        for (int kk = 0; kk < 5; kk++)
            swp[kk * 392 + j] = make_float4(w[(2 * kk) * 784 + f0],
                                            w[(2 * kk + 1) * 784 + f0],
                                            w[(2 * kk) * 784 + f1],
                                            w[(2 * kk + 1) * 784 + f1]);
    }
    __syncthreads();

    // ---- main loop ----
    const int warp = tid >> 5;
    const int lane = tid & 31;
    const int g = warp >> 1;        // row-group 0..3
    const int h = warp & 1;         // pixel-pair half
    const ull alp[2] = { pack2(s_al[0], s_al[1]), pack2(s_al[2], s_al[3]) };
    const ull bep[2] = { pack2(s_be[0], s_be[1]), pack2(s_be[2], s_be[3]) };
    const float2* xp2 = (const float2*)(x + ((size_t)blockIdx.x * 16 + g * 4) * 784);

    ull acc[4][5];
#pragma unroll
    for (int r = 0; r < 4; r++)
#pragma unroll
        for (int kk = 0; kk < 5; kk++) acc[r][kk] = 0ull;

    const int jbase = h * 196;      // this warp's 196 pairs; 7 iters (last masked)

    // prefetch iter 0
    float2 xv[4];
    {
        int j = jbase + lane;
#pragma unroll
        for (int r = 0; r < 4; r++) xv[r] = __ldg(&xp2[r * 392 + j]);
    }

#pragma unroll
    for (int t = 0; t < 7; t++) {
        const int j = jbase + t * 32 + lane;
        const bool valid = (t < 6) | (lane < 4);
        float2 cur[4];
#pragma unroll
        for (int r = 0; r < 4; r++) cur[r] = xv[r];
        // prefetch next iter (clamped for the masked tail)
        if (t < 6) {
            int jn = jbase + (t + 1) * 32 + lane;
            jn = (jn < jbase + 196) ? jn : jbase;
#pragma unroll
            for (int r = 0; r < 4; r++) xv[r] = __ldg(&xp2[r * 392 + jn]);
        }

        const int jc = valid ? j : jbase;
        int rowi = jc / 14;                 // 14 pairs per image row
        bool odd = rowi & 1;
        ull A = odd ? alp[1] : alp[0];
        ull B = odd ? bep[1] : bep[0];

        ull fd0[4], fd1[4];
#pragma unroll
        for (int r = 0; r < 4; r++) {
            float s0, c0, s1, c1;
            __sincosf(cur[r].x, &s0, &c0);
            __sincosf(cur[r].y, &s1, &c1);
            ull cs = pack2(c0, c1);
            ull sn = pack2(s0, s1);
            ull fvp = fma2(A, cs, mul2(B, sn));     // (fv0, fv1)
            float f0, f1;
            unpack2(fvp, f0, f1);
            f0 = valid ? f0 : 0.f;
            f1 = valid ? f1 : 0.f;
            fd0[r] = pack2(f0, f0);
            fd1[r] = pack2(f1, f1);
        }
#pragma unroll
        for (int kk = 0; kk < 5; kk++) {
            float4 wq = swp[kk * 392 + jc];         // LDS.128, conflict-free
            ull wv0 = pack2(wq.x, wq.y);
            ull wv1 = pack2(wq.z, wq.w);
#pragma unroll
            for (int r = 0; r < 4; r++)
                acc[r][kk] = fma2(fd1[r], wv1, fma2(fd0[r], wv0, acc[r][kk]));
        }
    }

    // ---- warp butterfly reduce (packed) ----
#pragma unroll
    for (int r = 0; r < 4; r++)
#pragma unroll
        for (int kk = 0; kk < 5; kk++) {
            ull v = acc[r][kk];
            v = add2(v, __shfl_xor_sync(0xFFFFFFFFu, v, 16));
            v = add2(v, __shfl_xor_sync(0xFFFFFFFFu, v, 8));
            v = add2(v, __shfl_xor_sync(0xFFFFFFFFu, v, 4));
            v = add2(v, __shfl_xor_sync(0xFFFFFFFFu, v, 2));
            v = add2(v, __shfl_xor_sync(0xFFFFFFFFu, v, 1));
            acc[r][kk] = v;
        }

    // extract class value per lane, stash partials
#pragma unroll
    for (int r = 0; r < 4; r++) {
        float myv = 0.f;
#pragma unroll
        for (int k = 0; k < 10; k++) {
            float lo, hi;
            unpack2(acc[r][k >> 1], lo, hi);
            float comp = (k & 1) ? hi : lo;
            if (lane == k) myv = comp;
        }
        if (lane < 10) sred[warp][r][lane] = myv;
    }
    __syncthreads();

    // ---- final: combine halves + log-softmax (16 threads, one per row) ----
    if (tid < 16) {
        int gg = tid >> 2, rr = tid & 3;
        float l[10];
#pragma unroll
        for (int k = 0; k < 10; k++)
            l[k] = sred[2 * gg][rr][k] + sred[2 * gg + 1][rr][k] + bias[k];
        float m = l[0];
#pragma unroll
        for (int k = 1; k < 10; k++) m = fmaxf(m, l[k]);
        float sum = 0.f;
#pragma unroll
        for (int k = 0; k < 10; k++) sum += __expf(l[k] - m);
        float lse = m + __logf(sum);
        size_t row = (size_t)blockIdx.x * 16 + gg * 4 + rr;
#pragma unroll
        for (int k = 0; k < 10; k++)
            out[row * 10 + k] = l[k] - lse;
    }
}

extern "C" void kernel_launch(void* const* d_in, const int* in_sizes, int n_in,
                              void* d_out, int out_size) {
    const float* x      = (const float*)d_in[0];   // (8192,1,28,28)
    const float* params = (const float*)d_in[1];   // (4,4,3)
    const float* w      = (const float*)d_in[2];   // (10,784)
    const float* bias   = (const float*)d_in[3];   // (10,)
    float* out          = (float*)d_out;           // (8192,10)

    quanv_fused<<<512, 256>>>(x, params, w, bias, out);
}

// round 11
// speedup vs baseline: 2.1376x; 1.0233x over previous
#include <cuda_runtime.h>
#include <math.h>

typedef unsigned long long ull;

__device__ __forceinline__ ull pack2(float lo, float hi) {
    ull r; asm("mov.b64 %0, {%1,%2};" : "=l"(r) : "f"(lo), "f"(hi)); return r;
}
__device__ __forceinline__ void unpack2(ull v, float& lo, float& hi) {
    asm("mov.b64 {%0,%1}, %2;" : "=f"(lo), "=f"(hi) : "l"(v));
}
__device__ __forceinline__ ull fma2(ull a, ull b, ull c) {
    ull d; asm("fma.rn.f32x2 %0, %1, %2, %3;" : "=l"(d) : "l"(a), "l"(b), "l"(c)); return d;
}
__device__ __forceinline__ ull mul2(ull a, ull b) {
    ull d; asm("mul.rn.f32x2 %0, %1, %2;" : "=l"(d) : "l"(a), "l"(b)); return d;
}
__device__ __forceinline__ ull add2(ull a, ull b) {
    ull d; asm("add.rn.f32x2 %0, %1, %2;" : "=l"(d) : "l"(a), "l"(b)); return d;
}

// Block = 16 batch rows. 8 warps, each warp owns 2 full rows (all 392 pixel
// pairs) -> no cross-warp reduction. Weights in smem pre-packed:
// swp[kk][pair] = float4(w[2kk][p0], w[2kk+1][p0], w[2kk][p1], w[2kk+1][p1]),
// read back as longlong2 = (wv0, wv1) ready for fma.rn.f32x2.
__global__ __launch_bounds__(256, 4)
void quanv_fused(const float* __restrict__ x,
                 const float* __restrict__ params,
                 const float* __restrict__ w,
                 const float* __restrict__ bias,
                 float* __restrict__ out) {
    __shared__ float4 swp4[5 * 392];    // 31360 B
    __shared__ float  s_al[4], s_be[4];

    const int tid = threadIdx.x;

    // ---- SU(2) observable coefficients: 4 threads, fast intrinsics ----
    if (tid < 4) {
        const int c = tid;
        float u00r = 1.f, u00i = 0.f, u01r = 0.f, u01i = 0.f;
        float u10r = 0.f, u10i = 0.f, u11r = 1.f, u11i = 0.f;
        for (int d = 0; d < 4; d++) {
            float rz1 = params[(d * 4 + c) * 3 + 0];
            float ry  = params[(d * 4 + c) * 3 + 1];
            float rz2 = params[(d * 4 + c) * 3 + 2];
            {
                float sp, cp; __sincosf(0.5f * rz1, &sp, &cp);
                float ci = -sp, cr = cp, t_;
                t_ = u00r * cr - u00i * ci; u00i = u00r * ci + u00i * cr; u00r = t_;
                t_ = u01r * cr - u01i * ci; u01i = u01r * ci + u01i * cr; u01r = t_;
                t_ = u10r * cr + u10i * ci; u10i = -u10r * ci + u10i * cr; u10r = t_;
                t_ = u11r * cr + u11i * ci; u11i = -u11r * ci + u11i * cr; u11r = t_;
            }
            {
                float ss, cc; __sincosf(0.5f * ry, &ss, &cc);
                float n00r = cc * u00r - ss * u10r, n00i = cc * u00i - ss * u10i;
                float n01r = cc * u01r - ss * u11r, n01i = cc * u01i - ss * u11i;
                float n10r = ss * u00r + cc * u10r, n10i = ss * u00i + cc * u10i;
                float n11r = ss * u01r + cc * u11r, n11i = ss * u01i + cc * u11i;
                u00r = n00r; u00i = n00i; u01r = n01r; u01i = n01i;
                u10r = n10r; u10i = n10i; u11r = n11r; u11i = n11i;
            }
            {
                float sp, cp; __sincosf(0.5f * rz2, &sp, &cp);
                float ci = -sp, cr = cp, t_;
                t_ = u00r * cr - u00i * ci; u00i = u00r * ci + u00i * cr; u00r = t_;
                t_ = u01r * cr - u01i * ci; u01i = u01r * ci + u01i * cr; u01r = t_;
                t_ = u10r * cr + u10i * ci; u10i = -u10r * ci + u10i * cr; u10r = t_;
                t_ = u11r * cr + u11i * ci; u11i = -u11r * ci + u11i * cr; u11r = t_;
            }
        }
        s_al[c] = (u00r * u00r + u00i * u00i) - (u10r * u10r + u10i * u10i);
        s_be[c] = (u00r * u01r + u00i * u01i) - (u10r * u11r + u10i * u11i);
    }

    // ---- permuted weights: pair j -> pixels (2j, 2j+1), same image row ----
    for (int j = tid; j < 392; j += 256) {
        int p0 = 2 * j;
        int r = p0 / 28, c = p0 - r * 28;                          // c even
        int f0 = ((r >> 1) * 14 + (c >> 1)) * 4 + ((r & 1) << 1);  // +(c&1)=0
        int f1 = f0 + 1;
#pragma unroll
        for (int kk = 0; kk < 5; kk++)
            swp4[kk * 392 + j] = make_float4(w[(2 * kk) * 784 + f0],
                                             w[(2 * kk + 1) * 784 + f0],
                                             w[(2 * kk) * 784 + f1],
                                             w[(2 * kk + 1) * 784 + f1]);
    }
    __syncthreads();

    const longlong2* swp = reinterpret_cast<const longlong2*>(swp4);

    // ---- main loop: warp owns rows (row0, row0+1), all 392 pairs ----
    const int warp = tid >> 5;
    const int lane = tid & 31;
    const ull alp[2] = { pack2(s_al[0], s_al[1]), pack2(s_al[2], s_al[3]) };
    const ull bep[2] = { pack2(s_be[0], s_be[1]), pack2(s_be[2], s_be[3]) };
    const size_t row0 = (size_t)blockIdx.x * 16 + warp * 2;
    const float2* xp2 = (const float2*)(x + row0 * 784);

    ull acc[2][5];
#pragma unroll
    for (int r = 0; r < 2; r++)
#pragma unroll
        for (int kk = 0; kk < 5; kk++) acc[r][kk] = 0ull;

    // prefetch iter 0
    float2 xv[2];
#pragma unroll
    for (int r = 0; r < 2; r++) xv[r] = __ldg(&xp2[r * 392 + lane]);

#pragma unroll 4
    for (int t = 0; t < 12; t++) {
        const int j = t * 32 + lane;
        float2 cur[2];
#pragma unroll
        for (int r = 0; r < 2; r++) cur[r] = xv[r];
        // prefetch next (t=11 prefetches the 8-lane tail, clamped)
        {
            int jn = j + 32;
            jn = (jn < 392) ? jn : 384;
#pragma unroll
            for (int r = 0; r < 2; r++) xv[r] = __ldg(&xp2[r * 392 + jn]);
        }

        int rowi = j / 14;                  // 14 pairs per image row
        ull A = (rowi & 1) ? alp[1] : alp[0];
        ull B = (rowi & 1) ? bep[1] : bep[0];

        ull fd0[2], fd1[2];
#pragma unroll
        for (int r = 0; r < 2; r++) {
            float s0, c0, s1, c1;
            __sincosf(cur[r].x, &s0, &c0);
            __sincosf(cur[r].y, &s1, &c1);
            ull fvp = fma2(A, pack2(c0, c1), mul2(B, pack2(s0, s1)));
            float f0, f1;
            unpack2(fvp, f0, f1);
            fd0[r] = pack2(f0, f0);
            fd1[r] = pack2(f1, f1);
        }
#pragma unroll
        for (int kk = 0; kk < 5; kk++) {
            longlong2 wv = swp[kk * 392 + j];   // LDS.128, conflict-free
#pragma unroll
            for (int r = 0; r < 2; r++)
                acc[r][kk] = fma2(fd1[r], (ull)wv.y,
                                  fma2(fd0[r], (ull)wv.x, acc[r][kk]));
        }
    }
    // tail: pairs 384..391, lanes 0..7 (image row 27 -> odd channels)
    {
        const bool valid = (lane < 8);
        const int j = 384 + (valid ? lane : 0);
        ull fd0[2], fd1[2];
#pragma unroll
        for (int r = 0; r < 2; r++) {
            float s0, c0, s1, c1;
            __sincosf(xv[r].x, &s0, &c0);
            __sincosf(xv[r].y, &s1, &c1);
            ull fvp = fma2(alp[1], pack2(c0, c1), mul2(bep[1], pack2(s0, s1)));
            float f0, f1;
            unpack2(fvp, f0, f1);
            f0 = valid ? f0 : 0.f;
            f1 = valid ? f1 : 0.f;
            fd0[r] = pack2(f0, f0);
            fd1[r] = pack2(f1, f1);
        }
#pragma unroll
        for (int kk = 0; kk < 5; kk++) {
            longlong2 wv = swp[kk * 392 + j];
#pragma unroll
            for (int r = 0; r < 2; r++)
                acc[r][kk] = fma2(fd1[r], (ull)wv.y,
                                  fma2(fd0[r], (ull)wv.x, acc[r][kk]));
        }
    }

    // ---- warp butterfly reduce (packed); afterwards every lane has totals ----
#pragma unroll
    for (int r = 0; r < 2; r++)
#pragma unroll
        for (int kk = 0; kk < 5; kk++) {
            ull v = acc[r][kk];
            v = add2(v, __shfl_xor_sync(0xFFFFFFFFu, v, 16));
            v = add2(v, __shfl_xor_sync(0xFFFFFFFFu, v, 8));
            v = add2(v, __shfl_xor_sync(0xFFFFFFFFu, v, 4));
            v = add2(v, __shfl_xor_sync(0xFFFFFFFFu, v, 2));
            v = add2(v, __shfl_xor_sync(0xFFFFFFFFu, v, 1));
            acc[r][kk] = v;
        }

    // ---- epilogue: lane 0 -> row0, lane 1 -> row0+1; log-softmax + store ----
    if (lane < 2) {
        const int r = lane;
        float l[10];
#pragma unroll
        for (int kk = 0; kk < 5; kk++) {
            float lo, hi;
            unpack2(acc[r][kk], lo, hi);
            l[2 * kk]     = lo + bias[2 * kk];
            l[2 * kk + 1] = hi + bias[2 * kk + 1];
        }
        float m = l[0];
#pragma unroll
        for (int k = 1; k < 10; k++) m = fmaxf(m, l[k]);
        float sum = 0.f;
#pragma unroll
        for (int k = 0; k < 10; k++) sum += __expf(l[k] - m);
        float lse = m + __logf(sum);
        float2* op = (float2*)(out + (row0 + r) * 10);
#pragma unroll
        for (int kk = 0; kk < 5; kk++)
            op[kk] = make_float2(l[2 * kk] - lse, l[2 * kk + 1] - lse);
    }
}

extern "C" void kernel_launch(void* const* d_in, const int* in_sizes, int n_in,
                              void* d_out, int out_size) {
    const float* x      = (const float*)d_in[0];   // (8192,1,28,28)
    const float* params = (const float*)d_in[1];   // (4,4,3)
    const float* w      = (const float*)d_in[2];   // (10,784)
    const float* bias   = (const float*)d_in[3];   // (10,)
    float* out          = (float*)d_out;           // (8192,10)

    quanv_fused<<<512, 256>>>(x, params, w, bias, out);
}